// round 7
// baseline (speedup 1.0000x reference)
#include <cuda_runtime.h>
#include <cstdint>

#define BB 256
#define LL 512
#define DD 64
#define NSPLIT 4
#define NBLK (BB * NSPLIT)          // 1024 blocks
#define ROWS 128                    // rows per block (quarter batch)
#define EPS_LOG 1e-7f
#define EPS_COS 1e-8f

__device__ float g_m[NBLK];
__device__ float g_pos[NBLK];
__device__ float g_neg[NBLK];
__device__ int   g_cnt = 0;

__device__ __forceinline__ void cp_async16(unsigned int dst, const void* src) {
    asm volatile("cp.async.cg.shared.global [%0], [%1], 16;" :: "r"(dst), "l"(src));
}

__global__ __launch_bounds__(256)
void wnl_fused(const float* __restrict__ emb,
               const float* __restrict__ probs,
               const float* __restrict__ labels,
               float* __restrict__ out)
{
    const int bid  = blockIdx.x;            // 0..1023
    const int b    = bid >> 2;              // batch
    const int qtr  = bid & 3;               // quarter
    const int tid  = threadIdx.x;           // 0..255
    const int wid  = tid >> 5;
    const int lane = tid & 31;

    __shared__ float4 tile[ROWS * 16];      // 32KB, XOR-swizzled
    __shared__ float4 s_qv[16];             // query row
    __shared__ float  sD[256], sN[256];
    __shared__ float  s_m[4], s_pos[4], s_neg[4];
    __shared__ float  s_nq;
    __shared__ int    s_last;

    const float* __restrict__ embB = emb    + (size_t)b * LL * DD;
    const float* __restrict__ labB = labels + (size_t)b * LL;
    const float* __restrict__ prbB = probs  + (size_t)b * LL;
    const int rowbase = qtr * ROWS;

    if (tid == 0) s_last = 0;

    // ---- stage q (16 chunks) and the 128x64 tile (2048 chunks) via cp.async ----
    if (tid < 16) {
        unsigned int dst = (unsigned int)__cvta_generic_to_shared(&s_qv[tid]);
        cp_async16(dst, (const char*)(embB + b * DD) + tid * 16);
    }
    {
        const char* srcBase = (const char*)(embB + (size_t)rowbase * DD);
        #pragma unroll
        for (int k = 0; k < 8; k++) {
            const int id = tid + k * 256;       // 16B-chunk id, 0..2047
            const int r  = id >> 4;
            const int j  = id & 15;
            unsigned int dst = (unsigned int)__cvta_generic_to_shared(
                               &tile[r * 16 + (j ^ (r & 15))]);
            cp_async16(dst, srcBase + (size_t)id * 16);  // fully coalesced
        }
    }
    asm volatile("cp.async.commit_group;");

    // ---- overlap: log terms for this quarter's 128 probs (MUFU under DRAM) ----
    float pos = 0.f, neg = 0.f, y = 0.f;
    if (tid < ROWS) {
        const int l = rowbase + tid;
        y = labB[l];                            // also the row mask label
        const float pe = prbB[l] + EPS_LOG;
        pos = y * logf(pe);
        neg = logf(1.0f - pe);
    }

    asm volatile("cp.async.wait_group 0;");
    __syncthreads();

    // ---- ||q|| by warp 0 (ready after next barrier) ----
    if (wid == 0) {
        float s = 0.f;
        if (lane < 16) {
            const float4 v = s_qv[lane];
            s = v.x*v.x + v.y*v.y + v.z*v.z + v.w*v.w;
        }
        #pragma unroll
        for (int o = 8; o; o >>= 1) s += __shfl_xor_sync(0xffffffffu, s, o);
        if (lane == 0) s_nq = sqrtf(s);
    }

    // ---- half-row dot+norm per thread, no shuffles ----
    const int r  = tid & 127;                   // row within tile
    const int hh = tid >> 7;                    // which half of the row
    float d = 0.f, n = 0.f;
    #pragma unroll
    for (int u = 0; u < 8; u++) {
        const int jj = hh * 8 + u;              // warp-uniform per instruction
        const float4 v = tile[r * 16 + (jj ^ (r & 15))];  // conflict-free
        const float4 q = s_qv[jj];              // broadcast
        d += q.x*v.x + q.y*v.y + q.z*v.z + q.w*v.w;
        n += v.x*v.x + v.y*v.y + v.z*v.z + v.w*v.w;
    }
    sD[tid] = d; sN[tid] = n;
    __syncthreads();

    // ---- per-row cos, relu, mask; then block reduce (threads 0..127) ----
    float m = 0.f;
    if (tid < ROWS) {
        const float dd = sD[tid] + sD[tid + 128];
        const float nn = sN[tid] + sN[tid + 128];
        const float cosv = dd / fmaxf(s_nq * sqrtf(nn), EPS_COS);
        m = fmaxf(cosv, 0.f) * y;               // relu * label (label==y here)
    }
    #pragma unroll
    for (int o = 16; o; o >>= 1) {
        m    = fmaxf(m, __shfl_xor_sync(0xffffffffu, m, o));
        pos += __shfl_xor_sync(0xffffffffu, pos, o);
        neg += __shfl_xor_sync(0xffffffffu, neg, o);
    }
    if (lane == 0 && wid < 4) { s_m[wid] = m; s_pos[wid] = pos; s_neg[wid] = neg; }
    __syncthreads();

    if (wid == 0) {
        float mm = (lane < 4) ? s_m[lane]   : 0.f;
        float pp = (lane < 4) ? s_pos[lane] : 0.f;
        float nn = (lane < 4) ? s_neg[lane] : 0.f;
        #pragma unroll
        for (int o = 2; o; o >>= 1) {
            mm = fmaxf(mm, __shfl_xor_sync(0xffffffffu, mm, o));
            pp += __shfl_xor_sync(0xffffffffu, pp, o);
            nn += __shfl_xor_sync(0xffffffffu, nn, o);
        }
        if (lane == 0) {
            g_m[bid] = mm; g_pos[bid] = pp; g_neg[bid] = nn;
            __threadfence();
            const int old = atomicAdd(&g_cnt, 1);
            if (old == NBLK - 1) s_last = 1;
        }
    }
    __syncthreads();

    // ---- last block: deterministic final combine ----
    if (s_last) {
        __threadfence();
        const int b2 = tid;                     // one batch per thread
        float mm = __ldcg(&g_m[4*b2]);
        float pp = __ldcg(&g_pos[4*b2]);
        float nn = __ldcg(&g_neg[4*b2]);
        #pragma unroll
        for (int j = 1; j < NSPLIT; j++) {
            mm = fmaxf(mm, __ldcg(&g_m[4*b2 + j]));
            pp += __ldcg(&g_pos[4*b2 + j]);
            nn += __ldcg(&g_neg[4*b2 + j]);
        }
        const float labdiag = __ldg(&labels[(size_t)b2 * LL + b2]);
        const float wnl = (labdiag == 0.f) ? mm : 0.f;
        float contrib = -pp - wnl * nn;

        #pragma unroll
        for (int o = 16; o; o >>= 1)
            contrib += __shfl_xor_sync(0xffffffffu, contrib, o);
        if (lane == 0) sD[wid] = contrib;       // reuse scratch
        __syncthreads();
        if (wid == 0) {
            float t = (lane < 8) ? sD[lane] : 0.f;
            #pragma unroll
            for (int o = 4; o; o >>= 1) t += __shfl_xor_sync(0xffffffffu, t, o);
            if (lane == 0) {
                out[0] = t / (float)BB;
                g_cnt = 0;                      // reset for next replay
            }
        }
    }
}

extern "C" void kernel_launch(void* const* d_in, const int* in_sizes, int n_in,
                              void* d_out, int out_size)
{
    const float* emb    = (const float*)d_in[0]; // (256, 512, 64) f32
    const float* probs  = (const float*)d_in[1]; // (256, 512) f32
    const float* labels = (const float*)d_in[2]; // (256, 512) f32
    float* out = (float*)d_out;                  // scalar f32

    wnl_fused<<<NBLK, 256>>>(emb, probs, labels, out);
}

// round 8
// speedup vs baseline: 1.4717x; 1.4717x over previous
#include <cuda_runtime.h>
#include <cstdint>

#define BB 256
#define LL 512
#define DD 64
#define NSPLIT 2
#define NBLK (BB * NSPLIT)        // 512 blocks
#define EPS_LOG 1e-7f
#define EPS_COS 1e-8f

__device__ float g_m[NBLK];
__device__ float g_pos[NBLK];
__device__ float g_neg[NBLK];
__device__ int   g_cnt = 0;

__global__ __launch_bounds__(256)
void wnl_fused(const float* __restrict__ emb,
               const float* __restrict__ probs,
               const float* __restrict__ labels,
               float* __restrict__ out)
{
    const int bid  = blockIdx.x;       // 0..511
    const int b    = bid >> 1;         // batch 0..255
    const int h    = bid & 1;          // half 0/1
    const int tid  = threadIdx.x;      // 0..255
    const int wid  = tid >> 5;         // 0..7
    const int lane = tid & 31;
    const int g    = lane >> 3;        // 4 row-groups per warp
    const int s    = lane & 7;         // 8 lanes per row

    __shared__ float s_m[8], s_pos[8], s_neg[8], s_sum[8];
    __shared__ int   s_last;

    const float* __restrict__ embB = emb    + (size_t)b * LL * DD;
    const float* __restrict__ labB = labels + (size_t)b * LL;
    const float* __restrict__ prbB = probs  + (size_t)b * LL;

    if (tid == 0) s_last = 0;

    // ---- mainloop with distance-2 pipelined loads (no prologue barrier) ----
    // warp covers rows rowBase..rowBase+32, 4 rows per iteration, 8 iterations
    const int rowBase = h * 256 + wid * 32;

    float4 pa[2], pb[2];               // prefetch buffers (distance 2)
    {
        const float* r0 = embB + (size_t)(rowBase + 0 * 4 + g) * DD;
        const float* r1 = embB + (size_t)(rowBase + 1 * 4 + g) * DD;
        pa[0] = *(const float4*)(r0 + s * 4);
        pb[0] = *(const float4*)(r0 + 32 + s * 4);
        pa[1] = *(const float4*)(r1 + s * 4);
        pb[1] = *(const float4*)(r1 + 32 + s * 4);
    }

    // q loaded per lane straight from GMEM (L1-resident after first warp)
    const float4 qa = *(const float4*)(embB + (size_t)b * DD + s * 4);
    const float4 qb = *(const float4*)(embB + (size_t)b * DD + 32 + s * 4);

    float nq2 = qa.x*qa.x + qa.y*qa.y + qa.z*qa.z + qa.w*qa.w
              + qb.x*qb.x + qb.y*qb.y + qb.z*qb.z + qb.w*qb.w;
    #pragma unroll
    for (int o = 4; o; o >>= 1) nq2 += __shfl_xor_sync(0xffffffffu, nq2, o);
    const float nq = sqrtf(nq2);

    float m = 0.f;
    #pragma unroll
    for (int it = 0; it < 8; it++) {
        const float4 xa = pa[it & 1];
        const float4 xb = pb[it & 1];
        if (it < 6) {                  // prefetch it+2 before reducing it
            const float* rp = embB + (size_t)(rowBase + (it + 2) * 4 + g) * DD;
            pa[it & 1] = *(const float4*)(rp + s * 4);
            pb[it & 1] = *(const float4*)(rp + 32 + s * 4);
        }
        float d = qa.x*xa.x + qa.y*xa.y + qa.z*xa.z + qa.w*xa.w
                + qb.x*xb.x + qb.y*xb.y + qb.z*xb.z + qb.w*xb.w;
        float n = xa.x*xa.x + xa.y*xa.y + xa.z*xa.z + xa.w*xa.w
                + xb.x*xb.x + xb.y*xb.y + xb.z*xb.z + xb.w*xb.w;
        #pragma unroll
        for (int o = 4; o; o >>= 1) {
            d += __shfl_xor_sync(0xffffffffu, d, o);
            n += __shfl_xor_sync(0xffffffffu, n, o);
        }
        const float lab  = __ldg(&labB[rowBase + it * 4 + g]);
        const float cosv = d / fmaxf(nq * sqrtf(n), EPS_COS);
        m = fmaxf(m, fmaxf(cosv, 0.f) * lab);
    }

    // ---- this half's log sums (one l per thread) ----
    const int   l  = h * 256 + tid;
    const float pe = prbB[l] + EPS_LOG;
    float pos = labB[l] * logf(pe);
    float neg = logf(1.0f - pe);

    // warp combine: max(m), sum(pos), sum(neg)
    #pragma unroll
    for (int o = 16; o; o >>= 1) {
        m    = fmaxf(m, __shfl_xor_sync(0xffffffffu, m, o));
        pos += __shfl_xor_sync(0xffffffffu, pos, o);
        neg += __shfl_xor_sync(0xffffffffu, neg, o);
    }
    if (lane == 0) { s_m[wid] = m; s_pos[wid] = pos; s_neg[wid] = neg; }
    __syncthreads();

    if (wid == 0) {
        float mm = (lane < 8) ? s_m[lane]   : 0.f;
        float pp = (lane < 8) ? s_pos[lane] : 0.f;
        float nn = (lane < 8) ? s_neg[lane] : 0.f;
        #pragma unroll
        for (int o = 4; o; o >>= 1) {
            mm = fmaxf(mm, __shfl_xor_sync(0xffffffffu, mm, o));
            pp += __shfl_xor_sync(0xffffffffu, pp, o);
            nn += __shfl_xor_sync(0xffffffffu, nn, o);
        }
        if (lane == 0) {
            g_m[bid] = mm; g_pos[bid] = pp; g_neg[bid] = nn;
            __threadfence();
            const int old = atomicAdd(&g_cnt, 1);
            if (old == NBLK - 1) s_last = 1;   // this block finishes the job
        }
    }
    __syncthreads();

    // ---- last-block final combine (deterministic fixed-order sum) ----
    if (s_last) {
        __threadfence();
        const int b2 = tid;                    // one batch per thread
        float mm = fmaxf(__ldcg(&g_m[2*b2]),  __ldcg(&g_m[2*b2+1]));
        float pp = __ldcg(&g_pos[2*b2]) + __ldcg(&g_pos[2*b2+1]);
        float nn = __ldcg(&g_neg[2*b2]) + __ldcg(&g_neg[2*b2+1]);
        const float labdiag = __ldg(&labels[(size_t)b2 * LL + b2]);
        const float wnl = (labdiag == 0.f) ? mm : 0.f;
        float contrib = -pp - wnl * nn;

        #pragma unroll
        for (int o = 16; o; o >>= 1)
            contrib += __shfl_xor_sync(0xffffffffu, contrib, o);
        if (lane == 0) s_sum[wid] = contrib;
        __syncthreads();
        if (wid == 0) {
            float t = (lane < 8) ? s_sum[lane] : 0.f;
            #pragma unroll
            for (int o = 4; o; o >>= 1) t += __shfl_xor_sync(0xffffffffu, t, o);
            if (lane == 0) {
                out[0] = t / (float)BB;
                g_cnt = 0;                     // reset for next graph replay
            }
        }
    }
}

extern "C" void kernel_launch(void* const* d_in, const int* in_sizes, int n_in,
                              void* d_out, int out_size)
{
    const float* emb    = (const float*)d_in[0]; // (256, 512, 64) f32
    const float* probs  = (const float*)d_in[1]; // (256, 512) f32
    const float* labels = (const float*)d_in[2]; // (256, 512) f32
    float* out = (float*)d_out;                  // scalar f32

    wnl_fused<<<NBLK, 256>>>(emb, probs, labels, out);
}

// round 9
// speedup vs baseline: 1.5013x; 1.0201x over previous
#include <cuda_runtime.h>
#include <cstdint>

#define BB 256
#define LL 512
#define DD 64
#define NSPLIT 2
#define NBLK (BB * NSPLIT)        // 512 blocks
#define EPS_LOG 1e-7f
#define EPS_COS 1e-8f

__device__ float g_m[NBLK];
__device__ float g_pos[NBLK];
__device__ float g_neg[NBLK];
__device__ int   g_cnt = 0;

__global__ __launch_bounds__(256)
void wnl_fused(const float* __restrict__ emb,
               const float* __restrict__ probs,
               const float* __restrict__ labels,
               float* __restrict__ out)
{
    const int bid  = blockIdx.x;       // 0..511
    const int b    = bid >> 1;         // batch 0..255
    const int h    = bid & 1;          // half 0/1
    const int tid  = threadIdx.x;      // 0..255
    const int wid  = tid >> 5;         // 0..7
    const int lane = tid & 31;
    const int g    = lane >> 3;        // 4 row-groups per warp
    const int s    = lane & 7;         // 8 lanes per row

    __shared__ float s_m[8], s_pos[8], s_neg[8], s_sum[8];
    __shared__ int   s_last;

    const float* __restrict__ embB = emb    + (size_t)b * LL * DD;
    const float* __restrict__ labB = labels + (size_t)b * LL;
    const float* __restrict__ prbB = probs  + (size_t)b * LL;

    if (tid == 0) s_last = 0;

    // If labels[b][b] != 0, the weak-negative weight is 0 -> the whole cosine
    // block for this batch is multiplied by zero. Skip all embedding reads.
    const float labdiag = __ldg(&labB[b]);

    float m = 0.f;
    if (labdiag == 0.f) {
        const int rowBase = h * 256 + wid * 32;   // warp covers 32 rows

        // all 32 row-labels for this warp in one coalesced load
        const float lv = labB[rowBase + lane];

        // query row per lane, straight from GMEM (L1-resident quickly)
        const float4 qa = *(const float4*)(embB + (size_t)b * DD + s * 4);
        const float4 qb = *(const float4*)(embB + (size_t)b * DD + 32 + s * 4);
        float nq2 = qa.x*qa.x + qa.y*qa.y + qa.z*qa.z + qa.w*qa.w
                  + qb.x*qb.x + qb.y*qb.y + qb.z*qb.z + qb.w*qb.w;
        #pragma unroll
        for (int o = 4; o; o >>= 1) nq2 += __shfl_xor_sync(0xffffffffu, nq2, o);
        const float nq = sqrtf(nq2);

        #pragma unroll
        for (int it = 0; it < 8; it++) {
            const int k = rowBase + it * 4 + g;
            // label broadcast from preloaded vector (no memory op)
            const float lab = __shfl_sync(0xffffffffu, lv, it * 4 + g);
            // rows with label 0 contribute exactly 0 -> skip their 256B load
            float4 xa = make_float4(0.f, 0.f, 0.f, 0.f);
            float4 xb = make_float4(0.f, 0.f, 0.f, 0.f);
            if (lab != 0.f) {
                const float* rp = embB + (size_t)k * DD;
                xa = *(const float4*)(rp + s * 4);
                xb = *(const float4*)(rp + 32 + s * 4);
            }
            float d = qa.x*xa.x + qa.y*xa.y + qa.z*xa.z + qa.w*xa.w
                    + qb.x*xb.x + qb.y*xb.y + qb.z*xb.z + qb.w*xb.w;
            float n = xa.x*xa.x + xa.y*xa.y + xa.z*xa.z + xa.w*xa.w
                    + xb.x*xb.x + xb.y*xb.y + xb.z*xb.z + xb.w*xb.w;
            #pragma unroll
            for (int o = 4; o; o >>= 1) {
                d += __shfl_xor_sync(0xffffffffu, d, o);
                n += __shfl_xor_sync(0xffffffffu, n, o);
            }
            const float cosv = d / fmaxf(nq * sqrtf(n), EPS_COS);
            m = fmaxf(m, fmaxf(cosv, 0.f) * lab);
        }
    }

    // ---- this half's log sums (one l per thread; always needed for pos) ----
    const int   l  = h * 256 + tid;
    const float pe = prbB[l] + EPS_LOG;
    float pos = labB[l] * logf(pe);
    float neg = logf(1.0f - pe);

    // warp combine: max(m), sum(pos), sum(neg)
    #pragma unroll
    for (int o = 16; o; o >>= 1) {
        m    = fmaxf(m, __shfl_xor_sync(0xffffffffu, m, o));
        pos += __shfl_xor_sync(0xffffffffu, pos, o);
        neg += __shfl_xor_sync(0xffffffffu, neg, o);
    }
    if (lane == 0) { s_m[wid] = m; s_pos[wid] = pos; s_neg[wid] = neg; }
    __syncthreads();

    if (wid == 0) {
        float mm = (lane < 8) ? s_m[lane]   : 0.f;
        float pp = (lane < 8) ? s_pos[lane] : 0.f;
        float nn = (lane < 8) ? s_neg[lane] : 0.f;
        #pragma unroll
        for (int o = 4; o; o >>= 1) {
            mm = fmaxf(mm, __shfl_xor_sync(0xffffffffu, mm, o));
            pp += __shfl_xor_sync(0xffffffffu, pp, o);
            nn += __shfl_xor_sync(0xffffffffu, nn, o);
        }
        if (lane == 0) {
            g_m[bid] = mm; g_pos[bid] = pp; g_neg[bid] = nn;
            __threadfence();
            const int old = atomicAdd(&g_cnt, 1);
            if (old == NBLK - 1) s_last = 1;   // this block finishes the job
        }
    }
    __syncthreads();

    // ---- last-block final combine (deterministic fixed-order sum) ----
    if (s_last) {
        __threadfence();
        const int b2 = tid;                    // one batch per thread
        float mm = fmaxf(__ldcg(&g_m[2*b2]),  __ldcg(&g_m[2*b2+1]));
        float pp = __ldcg(&g_pos[2*b2]) + __ldcg(&g_pos[2*b2+1]);
        float nn = __ldcg(&g_neg[2*b2]) + __ldcg(&g_neg[2*b2+1]);
        const float ld2 = __ldg(&labels[(size_t)b2 * LL + b2]);
        const float wnl = (ld2 == 0.f) ? mm : 0.f;
        float contrib = -pp - wnl * nn;

        #pragma unroll
        for (int o = 16; o; o >>= 1)
            contrib += __shfl_xor_sync(0xffffffffu, contrib, o);
        if (lane == 0) s_sum[wid] = contrib;
        __syncthreads();
        if (wid == 0) {
            float t = (lane < 8) ? s_sum[lane] : 0.f;
            #pragma unroll
            for (int o = 4; o; o >>= 1) t += __shfl_xor_sync(0xffffffffu, t, o);
            if (lane == 0) {
                out[0] = t / (float)BB;
                g_cnt = 0;                     // reset for next graph replay
            }
        }
    }
}

extern "C" void kernel_launch(void* const* d_in, const int* in_sizes, int n_in,
                              void* d_out, int out_size)
{
    const float* emb    = (const float*)d_in[0]; // (256, 512, 64) f32
    const float* probs  = (const float*)d_in[1]; // (256, 512) f32
    const float* labels = (const float*)d_in[2]; // (256, 512) f32
    float* out = (float*)d_out;                  // scalar f32

    wnl_fused<<<NBLK, 256>>>(emb, probs, labels, out);
}